// round 16
// baseline (speedup 1.0000x reference)
#include <cuda_runtime.h>

// Lower-triangular matvec: y[i] = sum_{j<=i} W[i,j] * x[j]
// n = 8192, W row-major fp32 (lower triangle = 128 MB, streamed once).
//
// R16 = R15 (prefetch.global.L2, 25.3us) + prefetch DISTANCE via a
// persistent grid. 888 blocks (148 SMs x 6, one resident wave); block g
// processes pairs g, g+888, ... While computing pair p it prefetches pair
// p+888's two rows (fire-and-forget, no regs/smem), so every pair after the
// first is consumed from L2 (~234 cyc) instead of raw DRAM (577+): R15's
// remaining per-block DRAM-latency ramp (prefetch distance ~0 at block
// start, ~1/8 of block life, x3.5 waves) disappears.
// L2 footprint: 888 x ~48-64KB ~ 43-57MB << 126MB; .cs keeps consumed W
// lines evict-first.

#define NTHREADS 256
#define GRID     888

__device__ __forceinline__ float dot4(float4 w, float4 v) {
    return w.x * v.x + w.y * v.y + w.z * v.z + w.w * v.w;
}

__device__ __forceinline__ void prefetch_l2(const void* p) {
    asm volatile("prefetch.global.L2 [%0];" :: "l"(p));
}

// Prefetch both rows of pair p (lines split across the block's 256 threads).
__device__ __forceinline__ void prefetch_pair(const float* __restrict__ W,
                                              int n, int p, int tid)
{
    const int r0 = p, r1 = n - 1 - p;
    const int lines0 = ((r0 + 1) * 4 + 127) >> 7;   // <= 256
    const int lines1 = ((n - p) * 4 + 127) >> 7;    // <= 256
    const char* p0 = (const char*)(W + (size_t)r0 * n);
    const char* p1 = (const char*)(W + (size_t)r1 * n);
    if (tid < lines0) prefetch_l2(p0 + (size_t)tid * 128);
    if (tid < lines1) prefetch_l2(p1 + (size_t)tid * 128);
}

// Partial dot of one W row (length len) with x — identical to R2/R15.
__device__ __forceinline__ float row_dot(const float* __restrict__ Wr,
                                         const float* __restrict__ x,
                                         const float4* __restrict__ x4,
                                         int len, int tid)
{
    const float4* __restrict__ W4 = reinterpret_cast<const float4*>(Wr);
    const int nv4 = len >> 2;

    float a0 = 0.0f, a1 = 0.0f, a2 = 0.0f, a3 = 0.0f;

    int k = tid;
    for (; k + 3 * NTHREADS < nv4; k += 4 * NTHREADS) {
        float4 w0 = __ldcs(W4 + k);
        float4 w1 = __ldcs(W4 + k + NTHREADS);
        float4 w2 = __ldcs(W4 + k + 2 * NTHREADS);
        float4 w3 = __ldcs(W4 + k + 3 * NTHREADS);
        float4 v0 = __ldg(x4 + k);
        float4 v1 = __ldg(x4 + k + NTHREADS);
        float4 v2 = __ldg(x4 + k + 2 * NTHREADS);
        float4 v3 = __ldg(x4 + k + 3 * NTHREADS);
        a0 += dot4(w0, v0);
        a1 += dot4(w1, v1);
        a2 += dot4(w2, v2);
        a3 += dot4(w3, v3);
    }
    #pragma unroll 1
    for (; k < nv4; k += NTHREADS) {
        a0 += dot4(__ldcs(W4 + k), __ldg(x4 + k));
    }

    float acc = (a0 + a1) + (a2 + a3);

    const int tail = len & 3;
    if (tid < tail) {
        const int j = (nv4 << 2) + tid;
        acc += Wr[j] * x[j];
    }
    return acc;
}

__global__ __launch_bounds__(NTHREADS)
void tril_mv_kernel(const float* __restrict__ x,
                    const float* __restrict__ W,
                    float* __restrict__ y,
                    int n)
{
    __shared__ float red0[NTHREADS / 32];
    __shared__ float red1[NTHREADS / 32];

    const int tid    = threadIdx.x;
    const int npairs = n >> 1;
    const float4* __restrict__ x4 = reinterpret_cast<const float4*>(x);

    // Prologue: prefetch this block's first pair.
    if (blockIdx.x < npairs) prefetch_pair(W, n, blockIdx.x, tid);

    for (int p = blockIdx.x; p < npairs; p += GRID) {
        const int r0 = p;
        const int r1 = n - 1 - p;

        float acc0 = row_dot(W + (size_t)r0 * n, x, x4, r0 + 1, tid);

        // Midpoint: request the next pair's rows now (fire-and-forget).
        // Remaining row r1 compute (~2.5us) >> DRAM latency, so pair p+GRID
        // will be L2-resident when we reach it.
        if (p + GRID < npairs) prefetch_pair(W, n, p + GRID, tid);

        float acc1 = row_dot(W + (size_t)r1 * n, x, x4, n - p, tid);

        // ---- dual block reduction ----
        #pragma unroll
        for (int off = 16; off > 0; off >>= 1) {
            acc0 += __shfl_down_sync(0xffffffffu, acc0, off);
            acc1 += __shfl_down_sync(0xffffffffu, acc1, off);
        }
        const int warp = tid >> 5;
        const int lane = tid & 31;
        if (lane == 0) { red0[warp] = acc0; red1[warp] = acc1; }
        __syncthreads();

        if (warp == 0) {
            float a0 = (lane < NTHREADS / 32) ? red0[lane] : 0.0f;
            float a1 = (lane < NTHREADS / 32) ? red1[lane] : 0.0f;
            #pragma unroll
            for (int off = (NTHREADS / 64); off > 0; off >>= 1) {
                a0 += __shfl_down_sync(0xffffffffu, a0, off);
                a1 += __shfl_down_sync(0xffffffffu, a1, off);
            }
            if (lane == 0) { y[r0] = a0; y[r1] = a1; }
        }
        __syncthreads();   // red0/red1 reuse guard
    }
}

extern "C" void kernel_launch(void* const* d_in, const int* in_sizes, int n_in,
                              void* d_out, int out_size) {
    const float* x = (const float*)d_in[0];   // [n]
    const float* W = (const float*)d_in[1];   // [n, n] row-major
    float*       y = (float*)d_out;           // [n]

    const int n = in_sizes[0];                // 8192 (even)

    tril_mv_kernel<<<GRID, NTHREADS>>>(x, W, y, n);
}

// round 17
// speedup vs baseline: 1.0152x; 1.0152x over previous
#include <cuda_runtime.h>

// Lower-triangular matvec: y[i] = sum_{j<=i} W[i,j] * x[j]
// n = 8192, W row-major fp32 (lower triangle = 128 MB, streamed once).
//
// R17 = R15 (block-per-pair + register-free prefetch.global.L2, 25.3us)
// + CROSS-WAVE prefetch distance: block b also prefetches the pair of block
// b+1184 (one residency wave ahead, ~1100 resident blocks). Wave w computes
// while wave w+1's W is pulled into L2 (~8us distance >> DRAM latency), so
// waves 2..4 consume L2 hits (~234cyc) instead of raw DRAM (577+). Persistent
// variants (R10/R14/R16) regressed -- block-per-pair + hints is the working
// structure; this adds distance without persistence. L2 budget ~75MB next-
// wave + residuals < 126MB; __ldcs keeps consumed lines evict-first.

#define NTHREADS 256
#define WAVE     1184      // ~one residency wave of blocks

__device__ __forceinline__ float dot4(float4 w, float4 v) {
    return w.x * v.x + w.y * v.y + w.z * v.z + w.w * v.w;
}

__device__ __forceinline__ void prefetch_l2(const void* p) {
    asm volatile("prefetch.global.L2 [%0];" :: "l"(p));
}

// Prefetch both rows of pair p (128B lines split across 256 threads).
__device__ __forceinline__ void prefetch_pair(const float* __restrict__ W,
                                              int n, int p, int tid)
{
    const int r0 = p, r1 = n - 1 - p;
    const int lines0 = ((r0 + 1) * 4 + 127) >> 7;   // <= 256
    const int lines1 = ((n - p) * 4 + 127) >> 7;    // <= 256
    const char* p0 = (const char*)(W + (size_t)r0 * n);
    const char* p1 = (const char*)(W + (size_t)r1 * n);
    if (tid < lines0) prefetch_l2(p0 + (size_t)tid * 128);
    if (tid < lines1) prefetch_l2(p1 + (size_t)tid * 128);
}

// Partial dot of one W row (length len) with x — identical to R2/R15.
__device__ __forceinline__ float row_dot(const float* __restrict__ Wr,
                                         const float* __restrict__ x,
                                         const float4* __restrict__ x4,
                                         int len, int tid)
{
    const float4* __restrict__ W4 = reinterpret_cast<const float4*>(Wr);
    const int nv4 = len >> 2;

    float a0 = 0.0f, a1 = 0.0f, a2 = 0.0f, a3 = 0.0f;

    int k = tid;
    for (; k + 3 * NTHREADS < nv4; k += 4 * NTHREADS) {
        float4 w0 = __ldcs(W4 + k);
        float4 w1 = __ldcs(W4 + k + NTHREADS);
        float4 w2 = __ldcs(W4 + k + 2 * NTHREADS);
        float4 w3 = __ldcs(W4 + k + 3 * NTHREADS);
        float4 v0 = __ldg(x4 + k);
        float4 v1 = __ldg(x4 + k + NTHREADS);
        float4 v2 = __ldg(x4 + k + 2 * NTHREADS);
        float4 v3 = __ldg(x4 + k + 3 * NTHREADS);
        a0 += dot4(w0, v0);
        a1 += dot4(w1, v1);
        a2 += dot4(w2, v2);
        a3 += dot4(w3, v3);
    }
    #pragma unroll 1
    for (; k < nv4; k += NTHREADS) {
        a0 += dot4(__ldcs(W4 + k), __ldg(x4 + k));
    }

    float acc = (a0 + a1) + (a2 + a3);

    const int tail = len & 3;
    if (tid < tail) {
        const int j = (nv4 << 2) + tid;
        acc += Wr[j] * x[j];
    }
    return acc;
}

__global__ __launch_bounds__(NTHREADS)
void tril_mv_kernel(const float* __restrict__ x,
                    const float* __restrict__ W,
                    float* __restrict__ y,
                    int n)
{
    __shared__ float red0[NTHREADS / 32];
    __shared__ float red1[NTHREADS / 32];

    const int b      = blockIdx.x;      // 0 .. n/2-1
    const int tid    = threadIdx.x;
    const int npairs = n >> 1;

    const int r0 = b;
    const int r1 = n - 1 - b;

    // Own pair: request full 64 KB now (covers wave 1 / scheduling slack).
    prefetch_pair(W, n, b, tid);
    // Next wave's pair: pulled into L2 while this block computes.
    if (b + WAVE < npairs) prefetch_pair(W, n, b + WAVE, tid);

    const float4* __restrict__ x4 = reinterpret_cast<const float4*>(x);

    float acc0 = row_dot(W + (size_t)r0 * n, x, x4, r0 + 1, tid);
    float acc1 = row_dot(W + (size_t)r1 * n, x, x4, n - b, tid);

    // ---- dual block reduction ----
    #pragma unroll
    for (int off = 16; off > 0; off >>= 1) {
        acc0 += __shfl_down_sync(0xffffffffu, acc0, off);
        acc1 += __shfl_down_sync(0xffffffffu, acc1, off);
    }
    const int warp = tid >> 5;
    const int lane = tid & 31;
    if (lane == 0) { red0[warp] = acc0; red1[warp] = acc1; }
    __syncthreads();

    if (warp == 0) {
        float a0 = (lane < NTHREADS / 32) ? red0[lane] : 0.0f;
        float a1 = (lane < NTHREADS / 32) ? red1[lane] : 0.0f;
        #pragma unroll
        for (int off = (NTHREADS / 64); off > 0; off >>= 1) {
            a0 += __shfl_down_sync(0xffffffffu, a0, off);
            a1 += __shfl_down_sync(0xffffffffu, a1, off);
        }
        if (lane == 0) { y[r0] = a0; y[r1] = a1; }
    }
}

extern "C" void kernel_launch(void* const* d_in, const int* in_sizes, int n_in,
                              void* d_out, int out_size) {
    const float* x = (const float*)d_in[0];   // [n]
    const float* W = (const float*)d_in[1];   // [n, n] row-major
    float*       y = (float*)d_out;           // [n]

    const int n = in_sizes[0];                // 8192 (even)

    tril_mv_kernel<<<n / 2, NTHREADS>>>(x, W, y, n);
}